// round 2
// baseline (speedup 1.0000x reference)
#include <cuda_runtime.h>
#include <math.h>

#define BATCH 8
#define TT 4096
#define NMELS 26
#define CONV_K 5
#define CH 64
#define WF 32
#define H1 256
#define H2 128
#define SHORT_W 8
#define SHORT_H 128

// scratch (device globals — no allocation allowed)
__device__ float g_xc[BATCH * TT * CH];   // conv output, relu'd
__device__ float g_a [BATCH * TT * CH];   // SE gate per (b,t,c)

// ---------------------------------------------------------------------------
// Kernel 1: causal conv1d (K=5, 26->64) + bias + relu
// grid: 8*64 blocks (64 tokens each), 256 threads
// ---------------------------------------------------------------------------
__global__ __launch_bounds__(256) void conv_kernel(
    const float* __restrict__ x, const float* __restrict__ cw,
    const float* __restrict__ cb)
{
    __shared__ float xsh[68 * NMELS];          // rows t0-4 .. t0+63
    __shared__ float wsh[CONV_K * NMELS * CH]; // 8320
    __shared__ float bsh[CH];

    const int b  = blockIdx.x >> 6;
    const int t0 = (blockIdx.x & 63) << 6;
    const int tid = threadIdx.x;

    for (int idx = tid; idx < 68 * NMELS; idx += 256) {
        int r = idx / NMELS, m = idx - r * NMELS;
        int t = t0 - 4 + r;
        xsh[idx] = (t >= 0) ? x[(b * TT + t) * NMELS + m] : 0.f;
    }
    for (int idx = tid; idx < CONV_K * NMELS * CH; idx += 256)
        wsh[idx] = cw[idx];
    if (tid < CH) bsh[tid] = cb[tid];
    __syncthreads();

    const int c  = tid & 63;
    const int tg = tid >> 6;   // 0..3, each handles 16 tokens

    float acc[16];
    #pragma unroll
    for (int i = 0; i < 16; ++i) acc[i] = bsh[c];

    #pragma unroll
    for (int k = 0; k < CONV_K; ++k) {
        #pragma unroll
        for (int m = 0; m < NMELS; ++m) {
            float w = wsh[(k * NMELS + m) * CH + c];
            int base = (tg * 16 + k) * NMELS + m;
            #pragma unroll
            for (int i = 0; i < 16; ++i)
                acc[i] = fmaf(xsh[base + i * NMELS], w, acc[i]);
        }
    }
    #pragma unroll
    for (int i = 0; i < 16; ++i) {
        int t = t0 + tg * 16 + i;
        g_xc[(b * TT + t) * CH + c] = fmaxf(acc[i], 0.f);
    }
}

// ---------------------------------------------------------------------------
// Kernel 2: SE gate. s = 32-frame causal mean of xc; a = sigmoid(relu(s@W1)@W2)
// grid: 8*32 blocks (128 tokens each), 256 threads, dynamic smem
// ---------------------------------------------------------------------------
__global__ __launch_bounds__(256) void se_kernel(
    const float* __restrict__ sew1, const float* __restrict__ seb1,
    const float* __restrict__ sew2, const float* __restrict__ seb2)
{
    extern __shared__ float sm2[];
    float* xsh = sm2;               // 159*64 = 10176
    float* ssh = sm2 + 10176;       // 128*65 = 8320 (padded stride 65)
    float* w1s = sm2 + 18496;       // 64*16
    float* w2s = sm2 + 19520;       // 16*64
    float* b1s = sm2 + 20544;       // 16
    float* b2s = sm2 + 20560;       // 64

    const int b  = blockIdx.x >> 5;
    const int t0 = (blockIdx.x & 31) << 7;
    const int tid = threadIdx.x;

    for (int idx = tid; idx < 159 * CH; idx += 256) {
        int r = idx >> 6, cc = idx & 63;
        int t = t0 - 31 + r;
        xsh[idx] = (t >= 0) ? g_xc[(b * TT + t) * CH + cc] : 0.f;
    }
    for (int idx = tid; idx < 1024; idx += 256) { w1s[idx] = sew1[idx]; w2s[idx] = sew2[idx]; }
    if (tid < 16) b1s[tid] = seb1[tid];
    if (tid < CH) b2s[tid] = seb2[tid];
    __syncthreads();

    // sliding 32-window sums: thread = (c, token-group of 32)
    {
        const int c  = tid & 63;
        const int tg = tid >> 6;
        const int tb = tg * 32;
        float ssum = 0.f;
        #pragma unroll
        for (int f = 0; f < WF; ++f) ssum += xsh[(tb + f) * CH + c];
        ssh[tb * 65 + c] = ssum * 0.03125f;
        for (int i = 1; i < 32; ++i) {
            ssum += xsh[(tb + i + 31) * CH + c] - xsh[(tb + i - 1) * CH + c];
            ssh[(tb + i) * 65 + c] = ssum * 0.03125f;
        }
    }
    __syncthreads();

    if (tid < 128) {
        const int t = tid;
        float hid[16];
        #pragma unroll
        for (int j = 0; j < 16; ++j) hid[j] = b1s[j];
        for (int cc = 0; cc < CH; ++cc) {
            float sv = ssh[t * 65 + cc];
            #pragma unroll
            for (int j = 0; j < 16; ++j) hid[j] = fmaf(sv, w1s[cc * 16 + j], hid[j]);
        }
        #pragma unroll
        for (int j = 0; j < 16; ++j) hid[j] = fmaxf(hid[j], 0.f);
        for (int cc = 0; cc < CH; ++cc) {
            float v = b2s[cc];
            #pragma unroll
            for (int j = 0; j < 16; ++j) v = fmaf(hid[j], w2s[j * CH + cc], v);
            g_a[(b * TT + t0 + t) * CH + cc] = 1.f / (1.f + expf(-v));
        }
    }
}

// ---------------------------------------------------------------------------
// Main fused kernel helpers: register-blocked GEMM with packed f32x2 FMA.
// Thread layout: 256 threads = 16(ty: token groups of 4) x 16(tx).
// Each thread owns tokens t = ty*4+i (i<4), columns j = tx*4 + 64*q + e.
// ---------------------------------------------------------------------------
__device__ __forceinline__ unsigned long long pack2(float lo, float hi) {
    unsigned long long r;
    asm("mov.b64 %0, {%1, %2};" : "=l"(r)
        : "r"(__float_as_uint(lo)), "r"(__float_as_uint(hi)));
    return r;
}
__device__ __forceinline__ void fma2(unsigned long long& d,
                                     unsigned long long a, unsigned long long b) {
    asm("fma.rn.f32x2 %0, %1, %2, %0;" : "+l"(d) : "l"(a), "l"(b));
}
__device__ __forceinline__ void unpack2(unsigned long long v, float& lo, float& hi) {
    unsigned int a, b2;
    asm("mov.b64 {%0, %1}, %2;" : "=r"(a), "=r"(b2) : "l"(v));
    lo = __uint_as_float(a); hi = __uint_as_float(b2);
}

// Gated-window GEMM: out[t][j] = relu( sum_{f>=F0,c} xc[t+f-31][c]*a[t][c]*W[(f-F0)*64+c][j] + bias[j] )
template<int NOUT, int F0>
__device__ __forceinline__ void gemm_gated(
    const float* __restrict__ Wg, const float* __restrict__ bias,
    const float* __restrict__ xs, const float* __restrict__ as_,
    float* __restrict__ wst, float* __restrict__ outp, int ostride, int tid)
{
    constexpr int KTOT = (WF - F0) * CH;
    constexpr int NCH  = KTOT / 32;
    constexpr int QN   = NOUT / 64;
    constexpr int LD4  = NOUT / 32;   // float4 per thread per 32-row chunk

    const int ty = tid >> 4, tx = tid & 15;

    unsigned long long acc[4][QN][2];
    #pragma unroll
    for (int i = 0; i < 4; ++i)
        #pragma unroll
        for (int q = 0; q < QN; ++q) { acc[i][q][0] = 0ull; acc[i][q][1] = 0ull; }

    // stage chunk 0
    {
        const float4* src = (const float4*)Wg;
        float4* dst = (float4*)wst;
        #pragma unroll
        for (int r = 0; r < LD4; ++r) dst[tid + 256 * r] = src[tid + 256 * r];
    }
    __syncthreads();

    for (int ch = 0; ch < NCH; ++ch) {
        float4 pre[LD4];
        if (ch + 1 < NCH) {
            const float4* src = (const float4*)(Wg + (ch + 1) * 32 * NOUT);
            #pragma unroll
            for (int r = 0; r < LD4; ++r) pre[r] = src[tid + 256 * r];
        }
        const float* wb = wst + (ch & 1) * (32 * NOUT);
        #pragma unroll
        for (int kk = 0; kk < 32; ++kk) {
            const int kp = ch * 32 + kk;
            const int f  = F0 + (kp >> 6);
            const int c  = kp & 63;
            unsigned long long avp[4];
            #pragma unroll
            for (int i = 0; i < 4; ++i) {
                int t = ty * 4 + i;
                float av = xs[(t + f) * CH + c] * as_[t * CH + c];
                avp[i] = pack2(av, av);
            }
            #pragma unroll
            for (int q = 0; q < QN; ++q) {
                float4 w4 = *(const float4*)(wb + kk * NOUT + tx * 4 + 64 * q);
                unsigned long long w01 = pack2(w4.x, w4.y);
                unsigned long long w23 = pack2(w4.z, w4.w);
                #pragma unroll
                for (int i = 0; i < 4; ++i) {
                    fma2(acc[i][q][0], avp[i], w01);
                    fma2(acc[i][q][1], avp[i], w23);
                }
            }
        }
        __syncthreads();
        if (ch + 1 < NCH) {
            float4* dst = (float4*)(wst + ((ch + 1) & 1) * (32 * NOUT));
            #pragma unroll
            for (int r = 0; r < LD4; ++r) dst[tid + 256 * r] = pre[r];
            __syncthreads();
        }
    }
    // epilogue: bias + relu -> smem
    #pragma unroll
    for (int i = 0; i < 4; ++i) {
        int t = ty * 4 + i;
        #pragma unroll
        for (int q = 0; q < QN; ++q) {
            #pragma unroll
            for (int p = 0; p < 2; ++p) {
                float v0, v1;
                unpack2(acc[i][q][p], v0, v1);
                int j0 = tx * 4 + 64 * q + p * 2;
                v0 = fmaxf(v0 + bias[j0], 0.f);
                v1 = fmaxf(v1 + bias[j0 + 1], 0.f);
                outp[t * ostride + j0]     = v0;
                outp[t * ostride + j0 + 1] = v1;
            }
        }
    }
}

// Plain GEMM from smem A (stride 256), K=256, NOUT=128, relu.
__device__ __forceinline__ void gemm_plain_h2(
    const float* __restrict__ Wg, const float* __restrict__ bias,
    const float* __restrict__ As, float* __restrict__ wst,
    float* __restrict__ outp, int ostride, int tid)
{
    constexpr int NOUT = 128, KTOT = 256, NCH = KTOT / 32, QN = 2, LD4 = 4;
    const int ty = tid >> 4, tx = tid & 15;

    unsigned long long acc[4][QN][2];
    #pragma unroll
    for (int i = 0; i < 4; ++i)
        #pragma unroll
        for (int q = 0; q < QN; ++q) { acc[i][q][0] = 0ull; acc[i][q][1] = 0ull; }

    {
        const float4* src = (const float4*)Wg;
        float4* dst = (float4*)wst;
        #pragma unroll
        for (int r = 0; r < LD4; ++r) dst[tid + 256 * r] = src[tid + 256 * r];
    }
    __syncthreads();

    for (int ch = 0; ch < NCH; ++ch) {
        float4 pre[LD4];
        if (ch + 1 < NCH) {
            const float4* src = (const float4*)(Wg + (ch + 1) * 32 * NOUT);
            #pragma unroll
            for (int r = 0; r < LD4; ++r) pre[r] = src[tid + 256 * r];
        }
        const float* wb = wst + (ch & 1) * (32 * NOUT);
        #pragma unroll
        for (int kk = 0; kk < 32; ++kk) {
            const int kp = ch * 32 + kk;
            unsigned long long avp[4];
            #pragma unroll
            for (int i = 0; i < 4; ++i) {
                int t = ty * 4 + i;
                float av = As[t * 256 + kp];
                avp[i] = pack2(av, av);
            }
            #pragma unroll
            for (int q = 0; q < QN; ++q) {
                float4 w4 = *(const float4*)(wb + kk * NOUT + tx * 4 + 64 * q);
                unsigned long long w01 = pack2(w4.x, w4.y);
                unsigned long long w23 = pack2(w4.z, w4.w);
                #pragma unroll
                for (int i = 0; i < 4; ++i) {
                    fma2(acc[i][q][0], avp[i], w01);
                    fma2(acc[i][q][1], avp[i], w23);
                }
            }
        }
        __syncthreads();
        if (ch + 1 < NCH) {
            float4* dst = (float4*)(wst + ((ch + 1) & 1) * (32 * NOUT));
            #pragma unroll
            for (int r = 0; r < LD4; ++r) dst[tid + 256 * r] = pre[r];
            __syncthreads();
        }
    }
    #pragma unroll
    for (int i = 0; i < 4; ++i) {
        int t = ty * 4 + i;
        #pragma unroll
        for (int q = 0; q < QN; ++q) {
            #pragma unroll
            for (int p = 0; p < 2; ++p) {
                float v0, v1;
                unpack2(acc[i][q][p], v0, v1);
                int j0 = tx * 4 + 64 * q + p * 2;
                v0 = fmaxf(v0 + bias[j0], 0.f);
                v1 = fmaxf(v1 + bias[j0 + 1], 0.f);
                outp[t * ostride + j0]     = v0;
                outp[t * ostride + j0 + 1] = v1;
            }
        }
    }
}

// ---------------------------------------------------------------------------
// Kernel 3: main fused kernel. grid 512 blocks x 64 tokens, 256 threads.
// dynamic smem layout (floats):
//   XS   = 0      : 95*64  = 6080     (xc rows t0-31..t0+63)   \ aliased by H2S later
//   AS   = 6080   : 64*64  = 4096                              /
//   H1S  = 10176  : 64*256 = 16384
//   HSS  = 26560  : 64*132 = 8448
//   WST  = 35008  : 2*32*256 = 16384  (double-buffer weight staging)
//   WOS  = 51392  : 512
//   total 51904 floats = 207616 B
// ---------------------------------------------------------------------------
#define OFF_XS  0
#define OFF_AS  6080
#define OFF_H2S 0
#define OFF_H1S 10176
#define OFF_HSS 26560
#define OFF_WST 35008
#define OFF_WOS 51392
#define SMEM3_FLOATS 51904

__global__ __launch_bounds__(256, 1) void main_kernel(
    const float* __restrict__ w1, const float* __restrict__ b1,
    const float* __restrict__ w2, const float* __restrict__ b2,
    const float* __restrict__ sw, const float* __restrict__ sb,
    const float* __restrict__ wo, const float* __restrict__ bo,
    float* __restrict__ out)
{
    extern __shared__ float sm[];
    const int b  = blockIdx.x >> 6;
    const int t0 = (blockIdx.x & 63) << 6;
    const int tid = threadIdx.x;

    // load xc slab (95 rows) and gate tile (64 rows)
    for (int idx = tid; idx < 95 * CH; idx += 256) {
        int r = idx >> 6, cc = idx & 63;
        int t = t0 - 31 + r;
        sm[OFF_XS + idx] = (t >= 0) ? g_xc[(b * TT + t) * CH + cc] : 0.f;
    }
    for (int idx = tid; idx < 64 * CH; idx += 256) {
        int r = idx >> 6, cc = idx & 63;
        sm[OFF_AS + idx] = g_a[(b * TT + t0 + r) * CH + cc];
    }
    for (int idx = tid; idx < 512; idx += 256) sm[OFF_WOS + idx] = wo[idx];
    __syncthreads();

    // phase 1: h1 = relu(flat_long @ w1 + b1)   (K=2048, N=256)
    gemm_gated<256, 0>(w1, b1, sm + OFF_XS, sm + OFF_AS,
                       sm + OFF_WST, sm + OFF_H1S, 256, tid);

    // phase 1b: h_short = relu(flat_short @ sw + sb)  (K=512, N=128, frames 24..31)
    gemm_gated<128, 24>(sw, sb, sm + OFF_XS, sm + OFF_AS,
                        sm + OFF_WST, sm + OFF_HSS, 132, tid);
    __syncthreads();  // before H2S aliases XS/AS

    // phase 2: h2 = relu(h1 @ w2 + b2)  (K=256, N=128)  — writes over XS/AS region
    gemm_plain_h2(w2, b2, sm + OFF_H1S, sm + OFF_WST, sm + OFF_H2S, 132, tid);
    __syncthreads();

    // phase 3: out = sigmoid([h2, h_short] @ wo + bo)
    if (tid < 128) {
        const int t = tid >> 1;
        const int o = tid & 1;
        float acc = bo[o];
        #pragma unroll 4
        for (int k = 0; k < 128; ++k)
            acc = fmaf(sm[OFF_H2S + t * 132 + k], sm[OFF_WOS + k * 2 + o], acc);
        #pragma unroll 4
        for (int k = 0; k < 128; ++k)
            acc = fmaf(sm[OFF_HSS + t * 132 + k], sm[OFF_WOS + (128 + k) * 2 + o], acc);
        out[(b * TT + t0 + t) * 2 + o] = 1.f / (1.f + expf(-acc));
    }
}

// ---------------------------------------------------------------------------
extern "C" void kernel_launch(void* const* d_in, const int* in_sizes, int n_in,
                              void* d_out, int out_size)
{
    const float* x      = (const float*)d_in[0];
    const float* conv_w = (const float*)d_in[1];
    const float* conv_b = (const float*)d_in[2];
    const float* se_w1  = (const float*)d_in[3];
    const float* se_b1  = (const float*)d_in[4];
    const float* se_w2  = (const float*)d_in[5];
    const float* se_b2  = (const float*)d_in[6];
    const float* w1     = (const float*)d_in[7];
    const float* b1     = (const float*)d_in[8];
    const float* w2     = (const float*)d_in[9];
    const float* b2     = (const float*)d_in[10];
    const float* sw     = (const float*)d_in[11];
    const float* sb     = (const float*)d_in[12];
    const float* wo     = (const float*)d_in[13];
    const float* bo     = (const float*)d_in[14];
    float* out = (float*)d_out;

    const int smem2 = 20624 * 4;
    const int smem3 = SMEM3_FLOATS * 4;
    cudaFuncSetAttribute(se_kernel,  cudaFuncAttributeMaxDynamicSharedMemorySize, smem2);
    cudaFuncSetAttribute(main_kernel, cudaFuncAttributeMaxDynamicSharedMemorySize, smem3);

    conv_kernel<<<BATCH * 64, 256>>>(x, conv_w, conv_b);
    se_kernel<<<BATCH * 32, 256, smem2>>>(se_w1, se_b1, se_w2, se_b2);
    main_kernel<<<BATCH * 64, 256, smem3>>>(w1, b1, w2, b2, sw, sb, wo, bo, out);
}

// round 6
// speedup vs baseline: 5.0770x; 5.0770x over previous
#include <cuda_runtime.h>
#include <cuda_fp16.h>
#include <math.h>
#include <stdint.h>

#define BATCH 8
#define TT 4096
#define NMELS 26
#define CONV_K 5
#define CH 64
#define WF 32

__device__ float g_xc[BATCH * TT * CH];
__device__ float g_a [BATCH * TT * CH];
__device__ uint4 g_w1h[65536];  // 32 chunks x 32KB fp16 swizzled [n256][k64]
__device__ uint4 g_swh[8192];   //  8 chunks x 16KB [n128][k64]
__device__ uint4 g_w2h[4096];   //  4 chunks x 16KB [n128][k64]

__device__ __forceinline__ uint32_t smem_u32(const void* p) {
    uint32_t a;
    asm("{ .reg .u64 t; cvta.to.shared.u64 t, %1; cvt.u32.u64 %0, t; }" : "=r"(a) : "l"(p));
    return a;
}
__device__ __forceinline__ uint32_t sw128(uint32_t o) { return o ^ ((o >> 3) & 0x70); }
__device__ __forceinline__ void ldsm4(uint32_t (&r)[4], uint32_t a) {
    asm volatile("ldmatrix.sync.aligned.m8n8.x4.shared.b16 {%0,%1,%2,%3}, [%4];"
                 : "=r"(r[0]), "=r"(r[1]), "=r"(r[2]), "=r"(r[3]) : "r"(a));
}
__device__ __forceinline__ void ldsm2(uint32_t (&r)[2], uint32_t a) {
    asm volatile("ldmatrix.sync.aligned.m8n8.x2.shared.b16 {%0,%1}, [%2];"
                 : "=r"(r[0]), "=r"(r[1]) : "r"(a));
}
__device__ __forceinline__ void mma16816(float (&d)[4], const uint32_t (&a)[4],
                                         const uint32_t (&b)[2]) {
    asm volatile("mma.sync.aligned.m16n8k16.row.col.f32.f16.f16.f32 "
                 "{%0,%1,%2,%3}, {%4,%5,%6,%7}, {%8,%9}, {%0,%1,%2,%3};"
                 : "+f"(d[0]), "+f"(d[1]), "+f"(d[2]), "+f"(d[3])
                 : "r"(a[0]), "r"(a[1]), "r"(a[2]), "r"(a[3]), "r"(b[0]), "r"(b[1]));
}

// ---------------------------------------------------------------------------
__global__ __launch_bounds__(256) void prep_kernel(
    const float* __restrict__ w1, const float* __restrict__ w2,
    const float* __restrict__ swp)
{
    int i = blockIdx.x * 256 + threadIdx.x;
    float v; unsigned short* dst;
    if (i < 524288) {
        int f = i >> 14, n = (i >> 6) & 255, kk = i & 63;
        v = w1[(f * 64 + kk) * 256 + n];
        dst = (unsigned short*)g_w1h + f * 16384 + (sw128(n * 128 + kk * 2) >> 1);
    } else if (i < 589824) {
        int r = i - 524288, j = r >> 13, n = (r >> 6) & 127, kk = r & 63;
        v = swp[(j * 64 + kk) * 128 + n];
        dst = (unsigned short*)g_swh + j * 8192 + (sw128(n * 128 + kk * 2) >> 1);
    } else {
        int r = i - 589824, c = r >> 13, n = (r >> 6) & 127, kk = r & 63;
        v = w2[(c * 64 + kk) * 128 + n];
        dst = (unsigned short*)g_w2h + c * 8192 + (sw128(n * 128 + kk * 2) >> 1);
    }
    *dst = __half_as_ushort(__float2half_rn(v));
}

// ---------------------------------------------------------------------------
__global__ __launch_bounds__(256, 2) void conv_kernel(
    const float* __restrict__ x, const float* __restrict__ cw, const float* __restrict__ cb)
{
    __shared__ float xsh[68 * NMELS];
    __shared__ float wsh[CONV_K * NMELS * CH];
    __shared__ float bsh[CH];
    const int b = blockIdx.x >> 6, t0 = (blockIdx.x & 63) << 6, tid = threadIdx.x;
    for (int idx = tid; idx < 68 * NMELS; idx += 256) {
        int r = idx / NMELS, m = idx - r * NMELS, t = t0 - 4 + r;
        xsh[idx] = (t >= 0) ? x[(b * TT + t) * NMELS + m] : 0.f;
    }
    for (int idx = tid; idx < CONV_K * NMELS * CH; idx += 256) wsh[idx] = cw[idx];
    if (tid < CH) bsh[tid] = cb[tid];
    __syncthreads();
    const int c = tid & 63, tg = tid >> 6;
    #pragma unroll
    for (int g = 0; g < 4; ++g) {
        float acc[4];
        #pragma unroll
        for (int i = 0; i < 4; ++i) acc[i] = bsh[c];
        #pragma unroll
        for (int k = 0; k < CONV_K; ++k)
            #pragma unroll
            for (int m = 0; m < NMELS; ++m) {
                float w = wsh[(k * NMELS + m) * CH + c];
                int base = (tg * 16 + g * 4 + k) * NMELS + m;
                #pragma unroll
                for (int i = 0; i < 4; ++i) acc[i] = fmaf(xsh[base + i * NMELS], w, acc[i]);
            }
        #pragma unroll
        for (int i = 0; i < 4; ++i)
            g_xc[(b * TT + t0 + tg * 16 + g * 4 + i) * CH + c] = fmaxf(acc[i], 0.f);
    }
}

// ---------------------------------------------------------------------------
__global__ __launch_bounds__(256) void se_kernel(
    const float* __restrict__ sew1, const float* __restrict__ seb1,
    const float* __restrict__ sew2, const float* __restrict__ seb2)
{
    extern __shared__ float sm2[];
    float* xsh = sm2; float* ssh = sm2 + 10176; float* w1s = sm2 + 18496;
    float* w2s = sm2 + 19520; float* b1s = sm2 + 20544; float* b2s = sm2 + 20560;
    const int b = blockIdx.x >> 5, t0 = (blockIdx.x & 31) << 7, tid = threadIdx.x;
    for (int idx = tid; idx < 159 * CH; idx += 256) {
        int r = idx >> 6, cc = idx & 63, t = t0 - 31 + r;
        xsh[idx] = (t >= 0) ? g_xc[(b * TT + t) * CH + cc] : 0.f;
    }
    for (int idx = tid; idx < 1024; idx += 256) { w1s[idx] = sew1[idx]; w2s[idx] = sew2[idx]; }
    if (tid < 16) b1s[tid] = seb1[tid];
    if (tid < CH) b2s[tid] = seb2[tid];
    __syncthreads();
    {
        const int c = tid & 63, tb = (tid >> 6) * 32;
        float s = 0.f;
        #pragma unroll
        for (int f = 0; f < WF; ++f) s += xsh[(tb + f) * CH + c];
        ssh[tb * 65 + c] = s * 0.03125f;
        for (int i = 1; i < 32; ++i) {
            s += xsh[(tb + i + 31) * CH + c] - xsh[(tb + i - 1) * CH + c];
            ssh[(tb + i) * 65 + c] = s * 0.03125f;
        }
    }
    __syncthreads();
    if (tid < 128) {
        float hid[16];
        #pragma unroll
        for (int j = 0; j < 16; ++j) hid[j] = b1s[j];
        for (int cc = 0; cc < CH; ++cc) {
            float sv = ssh[tid * 65 + cc];
            #pragma unroll
            for (int j = 0; j < 16; ++j) hid[j] = fmaf(sv, w1s[cc * 16 + j], hid[j]);
        }
        #pragma unroll
        for (int j = 0; j < 16; ++j) hid[j] = fmaxf(hid[j], 0.f);
        for (int cc = 0; cc < CH; ++cc) {
            float v = b2s[cc];
            #pragma unroll
            for (int j = 0; j < 16; ++j) v = fmaf(hid[j], w2s[j * CH + cc], v);
            g_a[(b * TT + t0 + tid) * CH + cc] = 1.f / (1.f + expf(-v));
        }
    }
}

// ---------------------------------------------------------------------------
// main kernel: 256 CTAs x 128 tokens, 512 threads (16 warps = 4M x 4N)
// smem floats: b1s@0(256) b2s@256(128) sbs@384(128) wos@512(512) acc2@1024(256)
//   XS@1280 (160 x stride68), GA@12160 (128 x stride68)
// smem bytes: AT@83456 (16K), BT@99840 (32K), H1@132608 (64K) -> total 198144
// ---------------------------------------------------------------------------
#define AT_B 83456
#define BT_B 99840
#define H1_B 132608
#define SMEM_TOT 198144

__device__ __forceinline__ void build_A(const float* smf, uint32_t smb, int f, int tid)
{
    int m = tid >> 2, kq = (tid & 3) << 4;
    const float* xp = smf + 1280 + (m + f) * 68 + kq;
    const float* gp = smf + 12160 + m * 68 + kq;
    uint32_t o = (uint32_t)(m * 128 + kq * 2);
    uint32_t dst0 = smb + AT_B + sw128(o);        // FIX: swizzle each 16B group
    uint32_t dst1 = smb + AT_B + sw128(o + 16);   //      independently
    uint32_t h[8];
    #pragma unroll
    for (int q = 0; q < 4; ++q) {
        float4 xv = *(const float4*)(xp + 4 * q);
        float4 gv = *(const float4*)(gp + 4 * q);
        float v0 = xv.x * gv.x, v1 = xv.y * gv.y, v2 = xv.z * gv.z, v3 = xv.w * gv.w;
        asm("cvt.rn.f16x2.f32 %0, %1, %2;" : "=r"(h[2 * q])     : "f"(v1), "f"(v0));
        asm("cvt.rn.f16x2.f32 %0, %1, %2;" : "=r"(h[2 * q + 1]) : "f"(v3), "f"(v2));
    }
    asm volatile("st.shared.v4.b32 [%0], {%1,%2,%3,%4};"
                 :: "r"(dst0), "r"(h[0]), "r"(h[1]), "r"(h[2]), "r"(h[3]));
    asm volatile("st.shared.v4.b32 [%0], {%1,%2,%3,%4};"
                 :: "r"(dst1), "r"(h[4]), "r"(h[5]), "r"(h[6]), "r"(h[7]));
}

template<int NT>
__device__ __forceinline__ void do_mma(uint32_t abase, uint32_t bbase,
                                       float (&c)[2][NT][4], int wm, int wn, int lane)
{
    uint32_t ra = (uint32_t)((wm * 32 + (lane & 15)) * 128 + ((lane >> 4) << 4));
    uint32_t rb = (uint32_t)((wn * (NT * 8) + (lane & 7)) * 128 + (((lane >> 3) & 1) << 4));
    #pragma unroll
    for (int ks = 0; ks < 4; ++ks) {
        uint32_t a0[4], a1[4];
        ldsm4(a0, abase + sw128(ra + ks * 32));
        ldsm4(a1, abase + sw128(ra + 2048 + ks * 32));
        #pragma unroll
        for (int nt = 0; nt < NT; ++nt) {
            uint32_t bf[2];
            ldsm2(bf, bbase + sw128(rb + nt * 1024 + ks * 32));
            mma16816(c[0][nt], a0, bf);
            mma16816(c[1][nt], a1, bf);
        }
    }
}

__device__ __forceinline__ void epi(float (&c)[2][4][4], const float* bias,
                                    const float* wop, float* acc2, int wm, int wn, int lane)
{
    float p[2][2][2];
    #pragma unroll
    for (int mt = 0; mt < 2; ++mt)
        #pragma unroll
        for (int h = 0; h < 2; ++h) { p[mt][h][0] = 0.f; p[mt][h][1] = 0.f; }
    #pragma unroll
    for (int mt = 0; mt < 2; ++mt)
    #pragma unroll
    for (int nt = 0; nt < 4; ++nt) {
        int col = wn * 32 + nt * 8 + 2 * (lane & 3);
        float b0 = bias[col], b1v = bias[col + 1];
        float w00 = wop[2 * col], w01 = wop[2 * col + 1];
        float w10 = wop[2 * col + 2], w11 = wop[2 * col + 3];
        float v;
        v = fmaxf(c[mt][nt][0] + b0, 0.f);  p[mt][0][0] += v * w00; p[mt][0][1] += v * w01;
        v = fmaxf(c[mt][nt][1] + b1v, 0.f); p[mt][0][0] += v * w10; p[mt][0][1] += v * w11;
        v = fmaxf(c[mt][nt][2] + b0, 0.f);  p[mt][1][0] += v * w00; p[mt][1][1] += v * w01;
        v = fmaxf(c[mt][nt][3] + b1v, 0.f); p[mt][1][0] += v * w10; p[mt][1][1] += v * w11;
    }
    #pragma unroll
    for (int mt = 0; mt < 2; ++mt)
        #pragma unroll
        for (int h = 0; h < 2; ++h)
            #pragma unroll
            for (int o = 0; o < 2; ++o) {
                p[mt][h][o] += __shfl_xor_sync(0xffffffffu, p[mt][h][o], 1);
                p[mt][h][o] += __shfl_xor_sync(0xffffffffu, p[mt][h][o], 2);
            }
    if ((lane & 3) == 0)
        #pragma unroll
        for (int mt = 0; mt < 2; ++mt)
            #pragma unroll
            for (int h = 0; h < 2; ++h) {
                int row = wm * 32 + mt * 16 + h * 8 + (lane >> 2);
                atomicAdd(&acc2[row * 2 + 0], p[mt][h][0]);
                atomicAdd(&acc2[row * 2 + 1], p[mt][h][1]);
            }
}

__global__ __launch_bounds__(512, 1) void main_kernel(
    const float* __restrict__ b1, const float* __restrict__ b2,
    const float* __restrict__ sb, const float* __restrict__ wo,
    const float* __restrict__ bo, float* __restrict__ out)
{
    extern __shared__ char smc[];
    float* smf = (float*)smc;
    const uint32_t smb = smem_u32(smc);
    const int tid = threadIdx.x, lane = tid & 31, wid = tid >> 5;
    const int wm = wid & 3, wn = wid >> 2;
    const int b = blockIdx.x >> 5, t0 = (blockIdx.x & 31) << 7;

    if (tid < 256) smf[tid] = b1[tid];
    if (tid < 128) { smf[256 + tid] = b2[tid]; smf[384 + tid] = sb[tid]; }
    smf[512 + tid] = wo[tid];
    if (tid < 256) smf[1024 + tid] = bo[tid & 1];
    for (int idx = tid; idx < 160 * 64; idx += 512) {
        int r = idx >> 6, c = idx & 63, t = t0 - 31 + r;
        smf[1280 + r * 68 + c] = (t >= 0) ? g_xc[(b * TT + t) * 64 + c] : 0.f;
    }
    for (int idx = tid; idx < 8192; idx += 512) {
        int r = idx >> 6, c = idx & 63;
        smf[12160 + r * 68 + c] = g_a[(b * TT + t0 + r) * 64 + c];
    }

    // ----- h1 pass: K=2048 over 32 frames, fp32 acc in registers -----------
    float c1[2][8][4];
    #pragma unroll
    for (int i = 0; i < 2; ++i)
        #pragma unroll
        for (int j = 0; j < 8; ++j)
            #pragma unroll
            for (int e = 0; e < 4; ++e) c1[i][j][e] = 0.f;

    uint4 pf[4];
    #pragma unroll
    for (int r = 0; r < 4; ++r) pf[r] = g_w1h[tid + 512 * r];
    for (int f = 0; f < 32; ++f) {
        __syncthreads();
        uint4* d = (uint4*)(smc + BT_B);
        #pragma unroll
        for (int r = 0; r < 4; ++r) d[tid + 512 * r] = pf[r];
        build_A(smf, smb, f, tid);
        if (f < 31)
            #pragma unroll
            for (int r = 0; r < 4; ++r) pf[r] = g_w1h[(f + 1) * 2048 + tid + 512 * r];
        __syncthreads();
        do_mma<8>(smb + AT_B, smb + BT_B, c1, wm, wn, lane);
    }

    // h1 epilogue: relu(+bias) -> fp16 H1 chunks
    #pragma unroll
    for (int mt = 0; mt < 2; ++mt)
    #pragma unroll
    for (int nt = 0; nt < 8; ++nt) {
        int colw = nt * 8 + 2 * (lane & 3);
        int colg = wn * 64 + colw;
        float b0v = smf[colg], b1v = smf[colg + 1];
        int r = wm * 32 + mt * 16 + (lane >> 2);
        uint32_t base = smb + H1_B + wn * 16384;
        float v0 = fmaxf(c1[mt][nt][0] + b0v, 0.f), v1 = fmaxf(c1[mt][nt][1] + b1v, 0.f);
        float v2 = fmaxf(c1[mt][nt][2] + b0v, 0.f), v3 = fmaxf(c1[mt][nt][3] + b1v, 0.f);
        uint32_t p0, p1;
        asm("cvt.rn.f16x2.f32 %0,%1,%2;" : "=r"(p0) : "f"(v1), "f"(v0));
        asm("cvt.rn.f16x2.f32 %0,%1,%2;" : "=r"(p1) : "f"(v3), "f"(v2));
        asm volatile("st.shared.b32 [%0], %1;" :: "r"(base + sw128(r * 128 + colw * 2)), "r"(p0));
        asm volatile("st.shared.b32 [%0], %1;" :: "r"(base + sw128((r + 8) * 128 + colw * 2)), "r"(p1));
    }

    // ----- short pass: frames 24..31, N=128 --------------------------------
    float cs[2][4][4];
    #pragma unroll
    for (int i = 0; i < 2; ++i)
        #pragma unroll
        for (int j = 0; j < 4; ++j)
            #pragma unroll
            for (int e = 0; e < 4; ++e) cs[i][j][e] = 0.f;
    pf[0] = g_swh[tid]; pf[1] = g_swh[tid + 512];
    for (int j = 0; j < 8; ++j) {
        __syncthreads();
        uint4* d = (uint4*)(smc + BT_B);
        d[tid] = pf[0]; d[tid + 512] = pf[1];
        build_A(smf, smb, 24 + j, tid);
        if (j < 7) { pf[0] = g_swh[(j + 1) * 1024 + tid]; pf[1] = g_swh[(j + 1) * 1024 + tid + 512]; }
        __syncthreads();
        do_mma<4>(smb + AT_B, smb + BT_B, cs, wm, wn, lane);
    }
    epi(cs, smf + 384, smf + 512 + 256, smf + 1024, wm, wn, lane);

    // ----- h2 pass: A = H1 fp16 chunks, K=256, N=128 ------------------------
    float ch[2][4][4];
    #pragma unroll
    for (int i = 0; i < 2; ++i)
        #pragma unroll
        for (int j = 0; j < 4; ++j)
            #pragma unroll
            for (int e = 0; e < 4; ++e) ch[i][j][e] = 0.f;
    pf[0] = g_w2h[tid]; pf[1] = g_w2h[tid + 512];
    for (int kc = 0; kc < 4; ++kc) {
        __syncthreads();
        uint4* d = (uint4*)(smc + BT_B);
        d[tid] = pf[0]; d[tid + 512] = pf[1];
        if (kc < 3) { pf[0] = g_w2h[(kc + 1) * 1024 + tid]; pf[1] = g_w2h[(kc + 1) * 1024 + tid + 512]; }
        __syncthreads();
        do_mma<4>(smb + H1_B + kc * 16384, smb + BT_B, ch, wm, wn, lane);
    }
    epi(ch, smf + 256, smf + 512, smf + 1024, wm, wn, lane);

    __syncthreads();
    if (tid < 128) {
        float a0 = smf[1024 + tid * 2], a1 = smf[1024 + tid * 2 + 1];
        float2 o;
        o.x = 1.f / (1.f + expf(-a0));
        o.y = 1.f / (1.f + expf(-a1));
        ((float2*)out)[b * TT + t0 + tid] = o;
    }
}

// ---------------------------------------------------------------------------
extern "C" void kernel_launch(void* const* d_in, const int* in_sizes, int n_in,
                              void* d_out, int out_size)
{
    const float* x      = (const float*)d_in[0];
    const float* conv_w = (const float*)d_in[1];
    const float* conv_b = (const float*)d_in[2];
    const float* se_w1  = (const float*)d_in[3];
    const float* se_b1  = (const float*)d_in[4];
    const float* se_w2  = (const float*)d_in[5];
    const float* se_b2  = (const float*)d_in[6];
    const float* w1     = (const float*)d_in[7];
    const float* b1     = (const float*)d_in[8];
    const float* w2     = (const float*)d_in[9];
    const float* b2     = (const float*)d_in[10];
    const float* sw     = (const float*)d_in[11];
    const float* sb     = (const float*)d_in[12];
    const float* wo     = (const float*)d_in[13];
    const float* bo     = (const float*)d_in[14];
    float* out = (float*)d_out;

    const int smem2 = 20624 * 4;
    cudaFuncSetAttribute(se_kernel, cudaFuncAttributeMaxDynamicSharedMemorySize, smem2);
    cudaFuncSetAttribute(main_kernel, cudaFuncAttributeMaxDynamicSharedMemorySize, SMEM_TOT);

    prep_kernel<<<2432, 256>>>(w1, w2, sw);
    conv_kernel<<<BATCH * 64, 256>>>(x, conv_w, conv_b);
    se_kernel<<<BATCH * 32, 256, smem2>>>(se_w1, se_b1, se_w2, se_b2);
    main_kernel<<<BATCH * 32, 512, SMEM_TOT>>>(b1, b2, sb, wo, bo, out);
}

// round 7
// speedup vs baseline: 7.4838x; 1.4741x over previous
#include <cuda_runtime.h>
#include <cuda_fp16.h>
#include <math.h>
#include <stdint.h>

#define BATCH 8
#define TT 4096
#define NMELS 26
#define CONV_K 5
#define CH 64
#define WF 32

__device__ float g_xc[BATCH * TT * CH];
__device__ float g_a [BATCH * TT * CH];
__device__ uint4 g_w1h[65536];  // 32 chunks x 32KB fp16 swizzled [n256][k64]
__device__ uint4 g_swh[8192];   //  8 chunks x 16KB [n128][k64]
__device__ uint4 g_w2h[4096];   //  4 chunks x 16KB [n128][k64]

__device__ __forceinline__ uint32_t smem_u32(const void* p) {
    uint32_t a;
    asm("{ .reg .u64 t; cvta.to.shared.u64 t, %1; cvt.u32.u64 %0, t; }" : "=r"(a) : "l"(p));
    return a;
}
__device__ __forceinline__ uint32_t sw128(uint32_t o) { return o ^ ((o >> 3) & 0x70); }
__device__ __forceinline__ void ldsm4(uint32_t (&r)[4], uint32_t a) {
    asm volatile("ldmatrix.sync.aligned.m8n8.x4.shared.b16 {%0,%1,%2,%3}, [%4];"
                 : "=r"(r[0]), "=r"(r[1]), "=r"(r[2]), "=r"(r[3]) : "r"(a));
}
__device__ __forceinline__ void mma16816(float (&d)[4], const uint32_t (&a)[4],
                                         uint32_t b0, uint32_t b1) {
    asm volatile("mma.sync.aligned.m16n8k16.row.col.f32.f16.f16.f32 "
                 "{%0,%1,%2,%3}, {%4,%5,%6,%7}, {%8,%9}, {%0,%1,%2,%3};"
                 : "+f"(d[0]), "+f"(d[1]), "+f"(d[2]), "+f"(d[3])
                 : "r"(a[0]), "r"(a[1]), "r"(a[2]), "r"(a[3]), "r"(b0), "r"(b1));
}
__device__ __forceinline__ void cp16(uint32_t dst, const void* src) {
    asm volatile("cp.async.cg.shared.global [%0], [%1], 16;" :: "r"(dst), "l"(src));
}
#define CP_COMMIT() asm volatile("cp.async.commit_group;" ::: "memory")
#define CP_WAIT(n)  asm volatile("cp.async.wait_group %0;" :: "n"(n) : "memory")

// ---------------------------------------------------------------------------
__global__ __launch_bounds__(256) void prep_kernel(
    const float* __restrict__ w1, const float* __restrict__ w2,
    const float* __restrict__ swp)
{
    int i = blockIdx.x * 256 + threadIdx.x;
    float v; unsigned short* dst;
    if (i < 524288) {
        int f = i >> 14, n = (i >> 6) & 255, kk = i & 63;
        v = w1[(f * 64 + kk) * 256 + n];
        dst = (unsigned short*)g_w1h + f * 16384 + (sw128(n * 128 + kk * 2) >> 1);
    } else if (i < 589824) {
        int r = i - 524288, j = r >> 13, n = (r >> 6) & 127, kk = r & 63;
        v = swp[(j * 64 + kk) * 128 + n];
        dst = (unsigned short*)g_swh + j * 8192 + (sw128(n * 128 + kk * 2) >> 1);
    } else {
        int r = i - 589824, c = r >> 13, n = (r >> 6) & 127, kk = r & 63;
        v = w2[(c * 64 + kk) * 128 + n];
        dst = (unsigned short*)g_w2h + c * 8192 + (sw128(n * 128 + kk * 2) >> 1);
    }
    *dst = __half_as_ushort(__float2half_rn(v));
}

// ---------------------------------------------------------------------------
__global__ __launch_bounds__(256, 2) void conv_kernel(
    const float* __restrict__ x, const float* __restrict__ cw, const float* __restrict__ cb)
{
    __shared__ float xsh[68 * NMELS];
    __shared__ float wsh[CONV_K * NMELS * CH];
    __shared__ float bsh[CH];
    const int b = blockIdx.x >> 6, t0 = (blockIdx.x & 63) << 6, tid = threadIdx.x;
    for (int idx = tid; idx < 68 * NMELS; idx += 256) {
        int r = idx / NMELS, m = idx - r * NMELS, t = t0 - 4 + r;
        xsh[idx] = (t >= 0) ? x[(b * TT + t) * NMELS + m] : 0.f;
    }
    for (int idx = tid; idx < CONV_K * NMELS * CH; idx += 256) wsh[idx] = cw[idx];
    if (tid < CH) bsh[tid] = cb[tid];
    __syncthreads();
    const int c = tid & 63, tg = tid >> 6;
    #pragma unroll
    for (int g = 0; g < 4; ++g) {
        float acc[4];
        #pragma unroll
        for (int i = 0; i < 4; ++i) acc[i] = bsh[c];
        #pragma unroll
        for (int k = 0; k < CONV_K; ++k)
            #pragma unroll
            for (int m = 0; m < NMELS; ++m) {
                float w = wsh[(k * NMELS + m) * CH + c];
                int base = (tg * 16 + g * 4 + k) * NMELS + m;
                #pragma unroll
                for (int i = 0; i < 4; ++i) acc[i] = fmaf(xsh[base + i * NMELS], w, acc[i]);
            }
        #pragma unroll
        for (int i = 0; i < 4; ++i)
            g_xc[(b * TT + t0 + tg * 16 + g * 4 + i) * CH + c] = fmaxf(acc[i], 0.f);
    }
}

// ---------------------------------------------------------------------------
__global__ __launch_bounds__(256) void se_kernel(
    const float* __restrict__ sew1, const float* __restrict__ seb1,
    const float* __restrict__ sew2, const float* __restrict__ seb2)
{
    extern __shared__ float sm2[];
    float* xsh = sm2; float* ssh = sm2 + 10176; float* w1s = sm2 + 18496;
    float* w2s = sm2 + 19520; float* b1s = sm2 + 20544; float* b2s = sm2 + 20560;
    const int b = blockIdx.x >> 5, t0 = (blockIdx.x & 31) << 7, tid = threadIdx.x;
    for (int idx = tid; idx < 159 * CH; idx += 256) {
        int r = idx >> 6, cc = idx & 63, t = t0 - 31 + r;
        xsh[idx] = (t >= 0) ? g_xc[(b * TT + t) * CH + cc] : 0.f;
    }
    for (int idx = tid; idx < 1024; idx += 256) { w1s[idx] = sew1[idx]; w2s[idx] = sew2[idx]; }
    if (tid < 16) b1s[tid] = seb1[tid];
    if (tid < CH) b2s[tid] = seb2[tid];
    __syncthreads();
    {
        const int c = tid & 63, tb = (tid >> 6) * 32;
        float s = 0.f;
        #pragma unroll
        for (int f = 0; f < WF; ++f) s += xsh[(tb + f) * CH + c];
        ssh[tb * 65 + c] = s * 0.03125f;
        for (int i = 1; i < 32; ++i) {
            s += xsh[(tb + i + 31) * CH + c] - xsh[(tb + i - 1) * CH + c];
            ssh[(tb + i) * 65 + c] = s * 0.03125f;
        }
    }
    __syncthreads();
    if (tid < 128) {
        float hid[16];
        #pragma unroll
        for (int j = 0; j < 16; ++j) hid[j] = b1s[j];
        for (int cc = 0; cc < CH; ++cc) {
            float sv = ssh[tid * 65 + cc];
            #pragma unroll
            for (int j = 0; j < 16; ++j) hid[j] = fmaf(sv, w1s[cc * 16 + j], hid[j]);
        }
        #pragma unroll
        for (int j = 0; j < 16; ++j) hid[j] = fmaxf(hid[j], 0.f);
        for (int cc = 0; cc < CH; ++cc) {
            float v = b2s[cc];
            #pragma unroll
            for (int j = 0; j < 16; ++j) v = fmaf(hid[j], w2s[j * CH + cc], v);
            g_a[(b * TT + t0 + tid) * CH + cc] = 1.f / (1.f + expf(-v));
        }
    }
}

// ---------------------------------------------------------------------------
// main kernel: 256 CTAs x 128 tokens, 512 threads (16 warps = 4M x 4N).
// smem bytes:
//   misc floats @0: b1s(0) b2s(256f) sbs(384f) wos(512f) acc2(1024f) -> 5120B
//   XSH @5120  : 160 rows x 72 halves fp16 = 23040
//   GAH @28160 : 128 rows x 72 halves fp16 = 18432
//   AT  @47104 : 3 x 16384 (A tile triple buffer)
//   BT  @96256 : 2 x 32768 (B slots 0,1)
//   H1  @161792: 64KB fp16 h1; first 32KB doubles as B slot 2 during h1 loop
//   total 227328
// ---------------------------------------------------------------------------
#define XSH_B 5120
#define GAH_B 28160
#define AT_B  47104
#define BT_B  96256
#define H1_B  161792
#define SMEM_TOT 227328

__device__ __forceinline__ uint32_t bslot(uint32_t smb, int s) {
    return smb + ((s == 2) ? H1_B : BT_B + (uint32_t)s * 32768u);
}

__device__ __forceinline__ void build_A(uint32_t smb, int f, int slot, int tid)
{
    const int m = tid >> 2, kq = (tid & 3) << 4;
    uint32_t xaddr = smb + XSH_B + (uint32_t)(((m + f) * 72 + kq) * 2);
    uint32_t gaddr = smb + GAH_B + (uint32_t)((m * 72 + kq) * 2);
    uint32_t o = (uint32_t)(m * 128 + kq * 2);
    uint32_t abase = smb + AT_B + (uint32_t)slot * 16384u;
    uint32_t dst0 = abase + sw128(o);
    uint32_t dst1 = abase + sw128(o + 16);
    uint32_t xv[8], gv[8], h[8];
    asm("ld.shared.v4.b32 {%0,%1,%2,%3}, [%4];"
        : "=r"(xv[0]), "=r"(xv[1]), "=r"(xv[2]), "=r"(xv[3]) : "r"(xaddr));
    asm("ld.shared.v4.b32 {%0,%1,%2,%3}, [%4];"
        : "=r"(xv[4]), "=r"(xv[5]), "=r"(xv[6]), "=r"(xv[7]) : "r"(xaddr + 16));
    asm("ld.shared.v4.b32 {%0,%1,%2,%3}, [%4];"
        : "=r"(gv[0]), "=r"(gv[1]), "=r"(gv[2]), "=r"(gv[3]) : "r"(gaddr));
    asm("ld.shared.v4.b32 {%0,%1,%2,%3}, [%4];"
        : "=r"(gv[4]), "=r"(gv[5]), "=r"(gv[6]), "=r"(gv[7]) : "r"(gaddr + 16));
    #pragma unroll
    for (int i = 0; i < 8; ++i)
        asm("mul.rn.f16x2 %0, %1, %2;" : "=r"(h[i]) : "r"(xv[i]), "r"(gv[i]));
    asm volatile("st.shared.v4.b32 [%0], {%1,%2,%3,%4};"
                 :: "r"(dst0), "r"(h[0]), "r"(h[1]), "r"(h[2]), "r"(h[3]));
    asm volatile("st.shared.v4.b32 [%0], {%1,%2,%3,%4};"
                 :: "r"(dst1), "r"(h[4]), "r"(h[5]), "r"(h[6]), "r"(h[7]));
}

template<int NT>
__device__ __forceinline__ void do_mma(uint32_t abase, uint32_t bbase,
                                       float (&c)[2][NT][4], int wm, int wn, int lane)
{
    uint32_t ra = (uint32_t)((wm * 32 + (lane & 15)) * 128 + ((lane >> 4) << 4));
    uint32_t rb = (uint32_t)((wn * (NT * 8) + (lane & 7) + ((lane >> 4) << 3)) * 128
                             + (((lane >> 3) & 1) << 4));
    #pragma unroll
    for (int ks = 0; ks < 4; ++ks) {
        uint32_t a0[4], a1[4];
        ldsm4(a0, abase + sw128(ra + ks * 32));
        ldsm4(a1, abase + sw128(ra + 2048 + ks * 32));
        #pragma unroll
        for (int nt = 0; nt < NT; nt += 2) {
            uint32_t b4[4];
            ldsm4(b4, bbase + sw128(rb + nt * 1024 + ks * 32));
            mma16816(c[0][nt], a0, b4[0], b4[1]);
            mma16816(c[1][nt], a1, b4[0], b4[1]);
            mma16816(c[0][nt + 1], a0, b4[2], b4[3]);
            mma16816(c[1][nt + 1], a1, b4[2], b4[3]);
        }
    }
}

__device__ __forceinline__ void epi(float (&c)[2][4][4], const float* bias,
                                    const float* wop, float* acc2, int wm, int wn, int lane)
{
    float p[2][2][2];
    #pragma unroll
    for (int mt = 0; mt < 2; ++mt)
        #pragma unroll
        for (int h = 0; h < 2; ++h) { p[mt][h][0] = 0.f; p[mt][h][1] = 0.f; }
    #pragma unroll
    for (int mt = 0; mt < 2; ++mt)
    #pragma unroll
    for (int nt = 0; nt < 4; ++nt) {
        int col = wn * 32 + nt * 8 + 2 * (lane & 3);
        float b0 = bias[col], b1v = bias[col + 1];
        float w00 = wop[2 * col], w01 = wop[2 * col + 1];
        float w10 = wop[2 * col + 2], w11 = wop[2 * col + 3];
        float v;
        v = fmaxf(c[mt][nt][0] + b0, 0.f);  p[mt][0][0] += v * w00; p[mt][0][1] += v * w01;
        v = fmaxf(c[mt][nt][1] + b1v, 0.f); p[mt][0][0] += v * w10; p[mt][0][1] += v * w11;
        v = fmaxf(c[mt][nt][2] + b0, 0.f);  p[mt][1][0] += v * w00; p[mt][1][1] += v * w01;
        v = fmaxf(c[mt][nt][3] + b1v, 0.f); p[mt][1][0] += v * w10; p[mt][1][1] += v * w11;
    }
    #pragma unroll
    for (int mt = 0; mt < 2; ++mt)
        #pragma unroll
        for (int h = 0; h < 2; ++h)
            #pragma unroll
            for (int o = 0; o < 2; ++o) {
                p[mt][h][o] += __shfl_xor_sync(0xffffffffu, p[mt][h][o], 1);
                p[mt][h][o] += __shfl_xor_sync(0xffffffffu, p[mt][h][o], 2);
            }
    if ((lane & 3) == 0)
        #pragma unroll
        for (int mt = 0; mt < 2; ++mt)
            #pragma unroll
            for (int h = 0; h < 2; ++h) {
                int row = wm * 32 + mt * 16 + h * 8 + (lane >> 2);
                atomicAdd(&acc2[row * 2 + 0], p[mt][h][0]);
                atomicAdd(&acc2[row * 2 + 1], p[mt][h][1]);
            }
}

__global__ __launch_bounds__(512, 1) void main_kernel(
    const float* __restrict__ b1, const float* __restrict__ b2,
    const float* __restrict__ sb, const float* __restrict__ wo,
    const float* __restrict__ bo, float* __restrict__ out)
{
    extern __shared__ char smc[];
    float* smf = (float*)smc;
    const uint32_t smb = smem_u32(smc);
    const int tid = threadIdx.x, lane = tid & 31, wid = tid >> 5;
    const int wm = wid & 3, wn = wid >> 2;
    const int b = blockIdx.x >> 5, t0 = (blockIdx.x & 31) << 7;
    __half* xsh = (__half*)(smc + XSH_B);
    __half* gah = (__half*)(smc + GAH_B);

    if (tid < 256) smf[tid] = b1[tid];
    if (tid < 128) { smf[256 + tid] = b2[tid]; smf[384 + tid] = sb[tid]; }
    smf[512 + tid] = wo[tid];
    if (tid < 256) smf[1024 + tid] = bo[tid & 1];
    for (int idx = tid; idx < 160 * 64; idx += 512) {
        int r = idx >> 6, c = idx & 63, t = t0 - 31 + r;
        xsh[r * 72 + c] = __float2half_rn((t >= 0) ? g_xc[(b * TT + t) * 64 + c] : 0.f);
    }
    for (int idx = tid; idx < 8192; idx += 512) {
        int r = idx >> 6, c = idx & 63;
        gah[r * 72 + c] = __float2half_rn(g_a[(b * TT + t0 + r) * 64 + c]);
    }
    __syncthreads();   // XSH/GAH ready for build_A

    // ----- h1 pass: K=2048 over 32 frames, pipelined ------------------------
    float c1[2][8][4];
    #pragma unroll
    for (int i = 0; i < 2; ++i)
        #pragma unroll
        for (int j = 0; j < 8; ++j)
            #pragma unroll
            for (int e = 0; e < 4; ++e) c1[i][j][e] = 0.f;

    {   // stage B(0) + A(0)
        uint32_t dst = bslot(smb, 0) + (uint32_t)tid * 16;
        const char* src = (const char*)g_w1h + (size_t)tid * 16;
        #pragma unroll
        for (int r = 0; r < 4; ++r) cp16(dst + r * 8192, src + (size_t)r * 8192);
        CP_COMMIT();
        build_A(smb, 0, 0, tid);
        CP_WAIT(0);
    }
    __syncthreads();
    for (int f = 0; f < 32; ++f) {
        if (f < 31) {
            int s = (f + 1) % 3;
            uint32_t dst = bslot(smb, s) + (uint32_t)tid * 16;
            const char* src = (const char*)g_w1h + (size_t)(f + 1) * 32768 + (size_t)tid * 16;
            #pragma unroll
            for (int r = 0; r < 4; ++r) cp16(dst + r * 8192, src + (size_t)r * 8192);
            CP_COMMIT();
            build_A(smb, f + 1, (f + 1) % 3, tid);
            CP_WAIT(1);
        }
        __syncthreads();
        do_mma<8>(smb + AT_B + (uint32_t)(f % 3) * 16384u, bslot(smb, f % 3),
                  c1, wm, wn, lane);
    }
    __syncthreads();   // all B-slot-2 (H1 alias) reads done before H1 writes

    // h1 epilogue: relu(+bias) -> fp16 H1 chunks
    #pragma unroll
    for (int mt = 0; mt < 2; ++mt)
    #pragma unroll
    for (int nt = 0; nt < 8; ++nt) {
        int colw = nt * 8 + 2 * (lane & 3);
        int colg = wn * 64 + colw;
        float b0v = smf[colg], b1v = smf[colg + 1];
        int r = wm * 32 + mt * 16 + (lane >> 2);
        uint32_t base = smb + H1_B + wn * 16384;
        float v0 = fmaxf(c1[mt][nt][0] + b0v, 0.f), v1 = fmaxf(c1[mt][nt][1] + b1v, 0.f);
        float v2 = fmaxf(c1[mt][nt][2] + b0v, 0.f), v3 = fmaxf(c1[mt][nt][3] + b1v, 0.f);
        uint32_t p0, p1;
        asm("cvt.rn.f16x2.f32 %0,%1,%2;" : "=r"(p0) : "f"(v1), "f"(v0));
        asm("cvt.rn.f16x2.f32 %0,%1,%2;" : "=r"(p1) : "f"(v3), "f"(v2));
        asm volatile("st.shared.b32 [%0], %1;" :: "r"(base + sw128(r * 128 + colw * 2)), "r"(p0));
        asm volatile("st.shared.b32 [%0], %1;" :: "r"(base + sw128((r + 8) * 128 + colw * 2)), "r"(p1));
    }

    // ----- short pass: frames 24..31, N=128, B in slot 0 --------------------
    float cs[2][4][4];
    #pragma unroll
    for (int i = 0; i < 2; ++i)
        #pragma unroll
        for (int j = 0; j < 4; ++j)
            #pragma unroll
            for (int e = 0; e < 4; ++e) cs[i][j][e] = 0.f;
    for (int j = 0; j < 8; ++j) {
        __syncthreads();
        {
            uint32_t dst = smb + BT_B + (uint32_t)tid * 16;
            const char* src = (const char*)g_swh + (size_t)j * 16384 + (size_t)tid * 16;
            cp16(dst, src); cp16(dst + 8192, src + 8192);
            CP_COMMIT();
        }
        build_A(smb, 24 + j, 0, tid);
        CP_WAIT(0);
        __syncthreads();
        do_mma<4>(smb + AT_B, smb + BT_B, cs, wm, wn, lane);
    }
    epi(cs, smf + 384, smf + 512 + 256, smf + 1024, wm, wn, lane);

    // ----- h2 pass: A = H1 fp16 chunks, K=256, N=128 ------------------------
    float ch[2][4][4];
    #pragma unroll
    for (int i = 0; i < 2; ++i)
        #pragma unroll
        for (int j = 0; j < 4; ++j)
            #pragma unroll
            for (int e = 0; e < 4; ++e) ch[i][j][e] = 0.f;
    for (int kc = 0; kc < 4; ++kc) {
        __syncthreads();
        {
            uint32_t dst = smb + BT_B + (uint32_t)tid * 16;
            const char* src = (const char*)g_w2h + (size_t)kc * 16384 + (size_t)tid * 16;
            cp16(dst, src); cp16(dst + 8192, src + 8192);
            CP_COMMIT();
        }
        CP_WAIT(0);
        __syncthreads();
        do_mma<4>(smb + H1_B + kc * 16384, smb + BT_B, ch, wm, wn, lane);
    }
    epi(ch, smf + 256, smf + 512, smf + 1024, wm, wn, lane);

    __syncthreads();
    if (tid < 128) {
        float a0 = smf[1024 + tid * 2], a1 = smf[1024 + tid * 2 + 1];
        float2 o;
        o.x = 1.f / (1.f + expf(-a0));
        o.y = 1.f / (1.f + expf(-a1));
        ((float2*)out)[b * TT + t0 + tid] = o;
    }
}

// ---------------------------------------------------------------------------
extern "C" void kernel_launch(void* const* d_in, const int* in_sizes, int n_in,
                              void* d_out, int out_size)
{
    const float* x      = (const float*)d_in[0];
    const float* conv_w = (const float*)d_in[1];
    const float* conv_b = (const float*)d_in[2];
    const float* se_w1  = (const float*)d_in[3];
    const float* se_b1  = (const float*)d_in[4];
    const float* se_w2  = (const float*)d_in[5];
    const float* se_b2  = (const float*)d_in[6];
    const float* w1     = (const float*)d_in[7];
    const float* b1     = (const float*)d_in[8];
    const float* w2     = (const float*)d_in[9];
    const float* b2     = (const float*)d_in[10];
    const float* sw     = (const float*)d_in[11];
    const float* sb     = (const float*)d_in[12];
    const float* wo     = (const float*)d_in[13];
    const float* bo     = (const float*)d_in[14];
    float* out = (float*)d_out;

    const int smem2 = 20624 * 4;
    cudaFuncSetAttribute(se_kernel, cudaFuncAttributeMaxDynamicSharedMemorySize, smem2);
    cudaFuncSetAttribute(main_kernel, cudaFuncAttributeMaxDynamicSharedMemorySize, SMEM_TOT);

    prep_kernel<<<2432, 256>>>(w1, w2, sw);
    conv_kernel<<<BATCH * 64, 256>>>(x, conv_w, conv_b);
    se_kernel<<<BATCH * 32, 256, smem2>>>(se_w1, se_b1, se_w2, se_b2);
    main_kernel<<<BATCH * 32, 512, SMEM_TOT>>>(b1, b2, sb, wo, bo, out);
}